// round 16
// baseline (speedup 1.0000x reference)
#include <cuda_runtime.h>
#include <cuda_fp16.h>
#include <cstdint>
#include <cstddef>

// INT4 packed linear: y[64, 28672] = x[64, 8192] @ dequant(w_packed, scales) + bias
// Harness canonicalizes fp16 tensors to float32 (lossless): x/scales/bias/out are f32.
// Math replicates reference: fp16 dequant ((nib-8)*s in fp16), fp32 MMA accum,
// fp16 rounding of y, fp16 bias add, upcast to f32 for the store.
//
// R16: warps split K x N (2x2) inside the CTA: each warp = 32 n-cols x half the
//      stage k-steps -> A-LDSM redundancy 4x -> 2x, cutting smem crossbar
//      traffic 29% (the measured L1 wall). CTA shape/copies/scaffold identical
//      to R10. kw-pair partials reduced via smem at the end.

#define K_DIM   8192
#define N_DIM   28672
#define M_DIM   64
#define BN      64            // columns per CTA (2 n-half-warps x 32 cols)
#define BK      64            // k per stage (32 packed rows); scale-group = 2 stages
#define NSTAGE  (K_DIM / BK)  // 128 stages
#define NBUF    4
#define XS_ELEMS (M_DIM * BK)        // 4096 halves = 8KB per buffer
#define WS_ELEMS ((BK / 2) * BN)     // 2048 ints  = 8KB per buffer
#define SMEM_BYTES (NBUF * (XS_ELEMS * 2 + WS_ELEMS * 4))   // 64KB

// fp16 copy of x (scratch via __device__ global)
__device__ __align__(16) __half g_xh[M_DIM * K_DIM];

__global__ void convert_x_kernel(const float* __restrict__ xf) {
    int base = blockIdx.x * blockDim.x + threadIdx.x;
    const int stride = 128 * 256;
#pragma unroll
    for (int it = 0; it < 4; ++it) {
        int i = (base + it * stride) * 4;
        float4 v = *reinterpret_cast<const float4*>(xf + i);
        *reinterpret_cast<__half2*>(&g_xh[i])     = __floats2half2_rn(v.x, v.y);
        *reinterpret_cast<__half2*>(&g_xh[i + 2]) = __floats2half2_rn(v.z, v.w);
    }
}

__device__ __forceinline__ unsigned smem_u32(const void* p) {
    return (unsigned)__cvta_generic_to_shared(p);
}

__device__ __forceinline__ void ldsm_x4(unsigned& r0, unsigned& r1, unsigned& r2, unsigned& r3,
                                        unsigned addr) {
    asm volatile("ldmatrix.sync.aligned.m8n8.x4.shared.b16 {%0,%1,%2,%3}, [%4];\n"
                 : "=r"(r0), "=r"(r1), "=r"(r2), "=r"(r3)
                 : "r"(addr));
}

__device__ __forceinline__ void mma_16816(float& c0, float& c1, float& c2, float& c3,
                                          unsigned a0, unsigned a1, unsigned a2, unsigned a3,
                                          unsigned b0, unsigned b1) {
    asm volatile("mma.sync.aligned.m16n8k16.row.col.f32.f16.f16.f32 "
                 "{%0,%1,%2,%3}, {%4,%5,%6,%7}, {%8,%9}, {%0,%1,%2,%3};\n"
                 : "+f"(c0), "+f"(c1), "+f"(c2), "+f"(c3)
                 : "r"(a0), "r"(a1), "r"(a2), "r"(a3), "r"(b0), "r"(b1));
}

__device__ __forceinline__ void cp_async16(unsigned saddr, const void* gaddr) {
    asm volatile("cp.async.cg.shared.global [%0], [%1], 16;\n"
                 :: "r"(saddr), "l"(gaddr));
}

// q in [0,256): fp16x2 {1024+lo, 1024+hi} - 1032 (exact), * scale (one fp16 rounding).
__device__ __forceinline__ unsigned dequant(unsigned q, __half2 s2) {
    unsigned t = ((q | (q << 12)) | 0x64006400u) & 0x640F640Fu;
    __half2 th = *reinterpret_cast<__half2*>(&t);
    const unsigned offc = 0x64086408u;  // half2 {1032, 1032}
    __half2 off = *reinterpret_cast<const __half2*>(&offc);
    __half2 wv = __hmul2(__hsub2(th, off), s2);
    return *reinterpret_cast<unsigned*>(&wv);
}

__global__ __launch_bounds__(128, 3)
void int4_linear_kernel(const int* __restrict__ w,
                        const float* __restrict__ scales,
                        const float* __restrict__ bias,
                        float* __restrict__ out) {
    // Dynamic SMEM: NBUF x { x tile 64x64 halves (swizzle B^=(row&7)<<4),
    //                        w tile 32x64 ints   (swizzle col^=(row&3)<<3) }
    extern __shared__ __align__(16) char smem_raw[];
    __half* xs_all = (__half*)smem_raw;                        // NBUF * 4096 halves
    int*    ws_all = (int*)(smem_raw + NBUF * XS_ELEMS * 2);   // NBUF * 2048 ints

    const int tid  = threadIdx.x;
    const int lane = tid & 31;
    const int warp = tid >> 5;
    const int kw   = warp >> 1;   // k-half of the stage this warp computes
    const int nw2  = warp & 1;    // n-half of the CTA tile
    const int r    = lane & 3;    // kh sub-row within B fragment
    const int c    = lane >> 2;   // n sub-col within n8 tile
    const int nbase = blockIdx.x * BN;
    const int col   = nbase + nw2 * 32 + c;
    int wcx[4];                   // swizzled frag columns, j = 0..3 (32 cols/warp)
#pragma unroll
    for (int j = 0; j < 4; ++j) wcx[j] = (nw2 * 32 + c + j * 8) ^ (r << 3);

    // accumulators: [m-subtile 0..3][n-subtile 0..3][frag 0..3]  (64 regs)
    float acc[4][4][4];
#pragma unroll
    for (int mi = 0; mi < 4; ++mi)
#pragma unroll
        for (int j = 0; j < 4; ++j)
#pragma unroll
            for (int f = 0; f < 4; ++f) acc[mi][j][f] = 0.0f;

    const int* wsrc = w + (size_t)blockIdx.x * BN;

    // stage copy: x tile (64x64 halves) + w tile (32x64 ints), one commit group
    auto copy_stage = [&](int g, int buf) {
        __half* xsb = xs_all + buf * XS_ELEMS;
        int*    wsb = ws_all + buf * WS_ELEMS;
#pragma unroll
        for (int i = 0; i < 4; ++i) {           // x: 512 chunks of 16B
            int idx = tid + i * 128;
            int row = idx >> 3;
            int cc  = idx & 7;
            unsigned boff = (unsigned)(row * 128 + cc * 16) ^ (unsigned)((row & 7) << 4);
            const __half* gp = g_xh + (size_t)row * K_DIM + (size_t)g * BK + cc * 8;
            cp_async16(smem_u32((const char*)xsb + boff), gp);
        }
#pragma unroll
        for (int i = 0; i < 4; ++i) {           // w: 512 chunks of 16B
            int idx = tid + i * 128;
            int row = idx >> 4;
            int cc  = idx & 15;
            int colw = (cc * 4) ^ ((row & 3) << 3);
            const int* gp = wsrc + (size_t)(g * (BK / 2) + row) * N_DIM + cc * 4;
            cp_async16(smem_u32(&wsb[row * BN + colw]), gp);
        }
        asm volatile("cp.async.commit_group;\n");
    };

    // fragment read: step t covers packed rows t*8 .. t*8+7; 32 cols per warp
    auto lds_w = [&](const int* wsb, int t, unsigned q[8]) {
        const int* p0 = wsb + (t * 8 + r) * BN;
        const int* p1 = p0 + 4 * BN;
#pragma unroll
        for (int j = 0; j < 4; ++j) {
            q[j]     = (unsigned)p0[wcx[j]];
            q[4 + j] = (unsigned)p1[wcx[j]];
        }
    };

    // ldmatrix per-thread terms
    const int row_l = lane & 15;
    const unsigned roff = (unsigned)(row_l * 128);
    const unsigned cb   = (unsigned)((lane >> 4) * 16);
    const unsigned sw   = (unsigned)((row_l & 7) << 4);
    unsigned xs_base[NBUF];
#pragma unroll
    for (int i = 0; i < NBUF; ++i) xs_base[i] = smem_u32(xs_all + i * XS_ELEMS);

    // prologue: 3 stages in flight
    copy_stage(0, 0);
    copy_stage(1, 1);
    copy_stage(2, 2);

    float sraw[4];
#pragma unroll
    for (int j = 0; j < 4; ++j)
        sraw[j] = __ldg(scales + col + j * 8);   // group 0

    __half2 s2[4];

    for (int g = 0; g < NSTAGE; ++g) {
        // ensure stage g's group has landed (exact tail handling)
        if (g < NSTAGE - 2)       asm volatile("cp.async.wait_group 2;\n");
        else if (g == NSTAGE - 2) asm volatile("cp.async.wait_group 1;\n");
        else                      asm volatile("cp.async.wait_group 0;\n");
        __syncthreads();

        // refill pipe (overwrites buffer of stage g-1; safe after the barrier)
        if (g + 3 < NSTAGE) copy_stage(g + 3, (g + 3) % NBUF);

        if ((g & 1) == 0) {
#pragma unroll
            for (int j = 0; j < 4; ++j)
                s2[j] = __half2half2(__float2half_rn(sraw[j]));
            int gn = (g >> 1) + 1;
            if (gn > 63) gn = 63;
#pragma unroll
            for (int j = 0; j < 4; ++j)
                sraw[j] = __ldg(scales + (size_t)gn * N_DIM + col + j * 8);
        }

        const int buf = g % NBUF;
        const unsigned sbase = xs_base[buf];
        const int* wsb = ws_all + buf * WS_ELEMS;

        // this warp's two k-steps: t = kw*2 + tt
        unsigned qc[8], qn[8];
        lds_w(wsb, kw * 2, qc);

#pragma unroll
        for (int tt = 0; tt < 2; ++tt) {
            const int t = kw * 2 + tt;
            if (tt == 0) lds_w(wsb, t + 1, qn);   // prefetch second step

            unsigned a[4][4];
#pragma unroll
            for (int mi = 0; mi < 4; ++mi) {
                unsigned addr = sbase + (unsigned)(mi * 2048) + roff +
                                (((unsigned)(t * 32) + cb) ^ sw);
                ldsm_x4(a[mi][0], a[mi][1], a[mi][2], a[mi][3], addr);
            }

#pragma unroll
            for (int j = 0; j < 4; ++j) {
                unsigned b0 = dequant(qc[j],     s2[j]);
                unsigned b1 = dequant(qc[4 + j], s2[j]);
#pragma unroll
                for (int mi = 0; mi < 4; ++mi)
                    mma_16816(acc[mi][j][0], acc[mi][j][1], acc[mi][j][2], acc[mi][j][3],
                              a[mi][0], a[mi][1], a[mi][2], a[mi][3], b0, b1);
            }
#pragma unroll
            for (int i = 0; i < 8; ++i) qc[i] = qn[i];
        }
    }

    // ---- kw-pair reduction: kw=1 warps stage partials, kw=0 warps add ----
    __syncthreads();                    // everyone done with pipeline buffers
    float* red = (float*)smem_raw;      // reuse smem; slot stride 65 (conflict-free)
    if (kw == 1) {
        float* dst = red + (size_t)(nw2 * 32 + lane) * 65;
        int idx = 0;
#pragma unroll
        for (int mi = 0; mi < 4; ++mi)
#pragma unroll
            for (int j = 0; j < 4; ++j)
#pragma unroll
                for (int f = 0; f < 4; ++f) dst[idx++] = acc[mi][j][f];
    }
    __syncthreads();
    if (kw == 0) {
        const float* src = red + (size_t)(nw2 * 32 + lane) * 65;
        int idx = 0;
#pragma unroll
        for (int mi = 0; mi < 4; ++mi)
#pragma unroll
            for (int j = 0; j < 4; ++j)
#pragma unroll
                for (int f = 0; f < 4; ++f) acc[mi][j][f] += src[idx++];

        // epilogue: fp32 acc -> fp16 round, + fp16 bias, upcast -> f32 store
#pragma unroll
        for (int mi = 0; mi < 4; ++mi) {
            int m0 = mi * 16 + (lane >> 2);
#pragma unroll
            for (int j = 0; j < 4; ++j) {
                int n = nbase + nw2 * 32 + j * 8 + 2 * (lane & 3);
                float2 bf = *reinterpret_cast<const float2*>(bias + n);
                __half2 bb = __floats2half2_rn(bf.x, bf.y);  // exact

                __half2 v0 = __halves2half2(__float2half_rn(acc[mi][j][0]),
                                            __float2half_rn(acc[mi][j][1]));
                v0 = __hadd2(v0, bb);
                float2 o0 = { __half2float(__low2half(v0)), __half2float(__high2half(v0)) };
                *reinterpret_cast<float2*>(out + (size_t)m0 * N_DIM + n) = o0;

                __half2 v1 = __halves2half2(__float2half_rn(acc[mi][j][2]),
                                            __float2half_rn(acc[mi][j][3]));
                v1 = __hadd2(v1, bb);
                float2 o1 = { __half2float(__low2half(v1)), __half2float(__high2half(v1)) };
                *reinterpret_cast<float2*>(out + (size_t)(m0 + 8) * N_DIM + n) = o1;
            }
        }
    }
}

extern "C" void kernel_launch(void* const* d_in, const int* in_sizes, int n_in,
                              void* d_out, int out_size) {
    const float* x      = (const float*)d_in[0];
    const int*   w      = (const int*)d_in[1];
    const float* scales = (const float*)d_in[2];
    const float* bias   = (const float*)d_in[3];
    float*       out    = (float*)d_out;

    cudaFuncSetAttribute(int4_linear_kernel,
                         cudaFuncAttributeMaxDynamicSharedMemorySize, SMEM_BYTES);

    convert_x_kernel<<<128, 256>>>(x);

    dim3 grid(N_DIM / BN);   // 448 CTAs (~3 per SM, balanced)
    int4_linear_kernel<<<grid, 128, SMEM_BYTES>>>(w, scales, bias, out);
}

// round 17
// speedup vs baseline: 1.0805x; 1.0805x over previous
#include <cuda_runtime.h>
#include <cuda_fp16.h>
#include <cstdint>
#include <cstddef>

// INT4 packed linear: y[64, 28672] = x[64, 8192] @ dequant(w_packed, scales) + bias
// Harness canonicalizes fp16 tensors to float32 (lossless): x/scales/bias/out are f32.
// Math replicates reference: fp16 dequant ((nib-8)*s in fp16), fp32 MMA accum,
// fp16 rounding of y, fp16 bias add, upcast to f32 for the store.
//
// R17: R10 loop with NBUF=3 (48KB dynamic smem) + __launch_bounds__(128,4) +
//      100% smem carveout -> target 4 CTAs/SM (16 warps) and full grid residency.
//      Stage loop unrolled by 3 for compile-time buffer indices.

#define K_DIM   8192
#define N_DIM   28672
#define M_DIM   64
#define BN      64            // columns per CTA (4 warps x 16 cols)
#define BK      64            // k per stage (32 packed rows); scale-group = 2 stages
#define NSTAGE  (K_DIM / BK)  // 128 stages
#define NBUF    3
#define XS_ELEMS (M_DIM * BK)        // 4096 halves = 8KB per buffer
#define WS_ELEMS ((BK / 2) * BN)     // 2048 ints  = 8KB per buffer
#define SMEM_BYTES (NBUF * (XS_ELEMS * 2 + WS_ELEMS * 4))   // 48KB

// fp16 copy of x (scratch via __device__ global)
__device__ __align__(16) __half g_xh[M_DIM * K_DIM];

__global__ void convert_x_kernel(const float* __restrict__ xf) {
    int base = blockIdx.x * blockDim.x + threadIdx.x;
    const int stride = 128 * 256;
#pragma unroll
    for (int it = 0; it < 4; ++it) {
        int i = (base + it * stride) * 4;
        float4 v = *reinterpret_cast<const float4*>(xf + i);
        *reinterpret_cast<__half2*>(&g_xh[i])     = __floats2half2_rn(v.x, v.y);
        *reinterpret_cast<__half2*>(&g_xh[i + 2]) = __floats2half2_rn(v.z, v.w);
    }
}

__device__ __forceinline__ unsigned smem_u32(const void* p) {
    return (unsigned)__cvta_generic_to_shared(p);
}

__device__ __forceinline__ void ldsm_x4(unsigned& r0, unsigned& r1, unsigned& r2, unsigned& r3,
                                        unsigned addr) {
    asm volatile("ldmatrix.sync.aligned.m8n8.x4.shared.b16 {%0,%1,%2,%3}, [%4];\n"
                 : "=r"(r0), "=r"(r1), "=r"(r2), "=r"(r3)
                 : "r"(addr));
}

__device__ __forceinline__ void mma_16816(float& c0, float& c1, float& c2, float& c3,
                                          unsigned a0, unsigned a1, unsigned a2, unsigned a3,
                                          unsigned b0, unsigned b1) {
    asm volatile("mma.sync.aligned.m16n8k16.row.col.f32.f16.f16.f32 "
                 "{%0,%1,%2,%3}, {%4,%5,%6,%7}, {%8,%9}, {%0,%1,%2,%3};\n"
                 : "+f"(c0), "+f"(c1), "+f"(c2), "+f"(c3)
                 : "r"(a0), "r"(a1), "r"(a2), "r"(a3), "r"(b0), "r"(b1));
}

__device__ __forceinline__ void cp_async16(unsigned saddr, const void* gaddr) {
    asm volatile("cp.async.cg.shared.global [%0], [%1], 16;\n"
                 :: "r"(saddr), "l"(gaddr));
}

// q in [0,256): fp16x2 {1024+lo, 1024+hi} - 1032 (exact), * scale (one fp16 rounding).
__device__ __forceinline__ unsigned dequant(unsigned q, __half2 s2) {
    unsigned t = ((q | (q << 12)) | 0x64006400u) & 0x640F640Fu;
    __half2 th = *reinterpret_cast<__half2*>(&t);
    const unsigned offc = 0x64086408u;  // half2 {1032, 1032}
    __half2 off = *reinterpret_cast<const __half2*>(&offc);
    __half2 wv = __hmul2(__hsub2(th, off), s2);
    return *reinterpret_cast<unsigned*>(&wv);
}

__global__ __launch_bounds__(128, 4)
void int4_linear_kernel(const int* __restrict__ w,
                        const float* __restrict__ scales,
                        const float* __restrict__ bias,
                        float* __restrict__ out) {
    // Dynamic SMEM: NBUF x { x tile 64x64 halves (swizzle B^=(row&7)<<4),
    //                        w tile 32x64 ints   (swizzle col^=(row&3)<<3) }
    extern __shared__ __align__(16) char smem_raw[];
    __half* xs_all = (__half*)smem_raw;                        // NBUF * 4096 halves
    int*    ws_all = (int*)(smem_raw + NBUF * XS_ELEMS * 2);   // NBUF * 2048 ints

    const int tid  = threadIdx.x;
    const int lane = tid & 31;
    const int warp = tid >> 5;
    const int r    = lane & 3;    // kh sub-row within B fragment
    const int c    = lane >> 2;   // n sub-col within n8 tile
    const int nwarp = blockIdx.x * BN + warp * 16;
    const int col   = nwarp + c;
    const int wc    = warp * 16 + c;                 // column word index in CTA tile
    const int wcx0 = wc ^ (r << 3);                  // swizzled frag columns
    const int wcx1 = (wc + 8) ^ (r << 3);

    float acc[4][2][4];
#pragma unroll
    for (int mi = 0; mi < 4; ++mi)
#pragma unroll
        for (int j = 0; j < 2; ++j)
#pragma unroll
            for (int f = 0; f < 4; ++f) acc[mi][j][f] = 0.0f;

    const int* wsrc = w + (size_t)blockIdx.x * BN;

    // stage copy: x tile (64x64 halves) + w tile (32x64 ints), one commit group
    auto copy_stage = [&](int g, int buf) {
        __half* xsb = xs_all + buf * XS_ELEMS;
        int*    wsb = ws_all + buf * WS_ELEMS;
#pragma unroll
        for (int i = 0; i < 4; ++i) {           // x: 512 chunks of 16B
            int idx = tid + i * 128;
            int row = idx >> 3;
            int cc  = idx & 7;
            unsigned boff = (unsigned)(row * 128 + cc * 16) ^ (unsigned)((row & 7) << 4);
            const __half* gp = g_xh + (size_t)row * K_DIM + (size_t)g * BK + cc * 8;
            cp_async16(smem_u32((const char*)xsb + boff), gp);
        }
#pragma unroll
        for (int i = 0; i < 4; ++i) {           // w: 512 chunks of 16B
            int idx = tid + i * 128;
            int row = idx >> 4;
            int cc  = idx & 15;
            int colw = (cc * 4) ^ ((row & 3) << 3);
            const int* gp = wsrc + (size_t)(g * (BK / 2) + row) * N_DIM + cc * 4;
            cp_async16(smem_u32(&wsb[row * BN + colw]), gp);
        }
        asm volatile("cp.async.commit_group;\n");
    };

    // fragment read from staged weights: step t covers packed rows t*8 .. t*8+7
    auto lds_w = [&](const int* wsb, int t, unsigned q[4]) {
        const int* p0 = wsb + (t * 8 + r) * BN;
        const int* p1 = p0 + 4 * BN;
        q[0] = (unsigned)p0[wcx0];
        q[1] = (unsigned)p0[wcx1];
        q[2] = (unsigned)p1[wcx0];
        q[3] = (unsigned)p1[wcx1];
    };

    // ldmatrix per-thread terms
    const int row_l = lane & 15;
    const unsigned roff = (unsigned)(row_l * 128);
    const unsigned cb   = (unsigned)((lane >> 4) * 16);
    const unsigned sw   = (unsigned)((row_l & 7) << 4);
    unsigned xs_base[NBUF];
#pragma unroll
    for (int i = 0; i < NBUF; ++i) xs_base[i] = smem_u32(xs_all + i * XS_ELEMS);

    // prologue: 2 stages in flight (depth-2, NBUF=3)
    copy_stage(0, 0);
    copy_stage(1, 1);

    float sraw[2];
#pragma unroll
    for (int j = 0; j < 2; ++j)
        sraw[j] = __ldg(scales + col + j * 8);   // group 0

    __half2 s2[2];

#pragma unroll 3
    for (int g = 0; g < NSTAGE; ++g) {
        if (g < NSTAGE - 1) asm volatile("cp.async.wait_group 1;\n");
        else                asm volatile("cp.async.wait_group 0;\n");
        __syncthreads();

        // refill pipe (overwrites buffer of stage g-1; safe after the barrier)
        if (g + 2 < NSTAGE) copy_stage(g + 2, (g + 2) % NBUF);

        if ((g & 1) == 0) {
#pragma unroll
            for (int j = 0; j < 2; ++j)
                s2[j] = __half2half2(__float2half_rn(sraw[j]));
            int gn = (g >> 1) + 1;
            if (gn > 63) gn = 63;
#pragma unroll
            for (int j = 0; j < 2; ++j)
                sraw[j] = __ldg(scales + (size_t)gn * N_DIM + col + j * 8);
        }

        const int buf = g % NBUF;
        const unsigned sbase = xs_base[buf];
        const int* wsb = ws_all + buf * WS_ELEMS;

        unsigned qc[4], qn[4];
        lds_w(wsb, 0, qc);

#pragma unroll
        for (int t = 0; t < 4; ++t) {
            if (t < 3) lds_w(wsb, t + 1, qn);   // prefetch next step's frags

            unsigned a[4][4];
#pragma unroll
            for (int mi = 0; mi < 4; ++mi) {
                unsigned addr = sbase + (unsigned)(mi * 2048) + roff +
                                (((unsigned)(t * 32) + cb) ^ sw);
                ldsm_x4(a[mi][0], a[mi][1], a[mi][2], a[mi][3], addr);
            }

#pragma unroll
            for (int j = 0; j < 2; ++j) {
                unsigned b0 = dequant(qc[j],     s2[j]);
                unsigned b1 = dequant(qc[2 + j], s2[j]);
#pragma unroll
                for (int mi = 0; mi < 4; ++mi)
                    mma_16816(acc[mi][j][0], acc[mi][j][1], acc[mi][j][2], acc[mi][j][3],
                              a[mi][0], a[mi][1], a[mi][2], a[mi][3], b0, b1);
            }
#pragma unroll
            for (int i = 0; i < 4; ++i) qc[i] = qn[i];
        }
    }

    // epilogue: fp32 acc -> fp16 round, + fp16 bias, upcast -> f32 store
#pragma unroll
    for (int mi = 0; mi < 4; ++mi) {
        int m0 = mi * 16 + (lane >> 2);
#pragma unroll
        for (int j = 0; j < 2; ++j) {
            int n = nwarp + j * 8 + 2 * (lane & 3);
            float2 bf = *reinterpret_cast<const float2*>(bias + n);
            __half2 bb = __floats2half2_rn(bf.x, bf.y);  // exact

            __half2 v0 = __halves2half2(__float2half_rn(acc[mi][j][0]),
                                        __float2half_rn(acc[mi][j][1]));
            v0 = __hadd2(v0, bb);
            float2 o0 = { __half2float(__low2half(v0)), __half2float(__high2half(v0)) };
            *reinterpret_cast<float2*>(out + (size_t)m0 * N_DIM + n) = o0;

            __half2 v1 = __halves2half2(__float2half_rn(acc[mi][j][2]),
                                        __float2half_rn(acc[mi][j][3]));
            v1 = __hadd2(v1, bb);
            float2 o1 = { __half2float(__low2half(v1)), __half2float(__high2half(v1)) };
            *reinterpret_cast<float2*>(out + (size_t)(m0 + 8) * N_DIM + n) = o1;
        }
    }
}

extern "C" void kernel_launch(void* const* d_in, const int* in_sizes, int n_in,
                              void* d_out, int out_size) {
    const float* x      = (const float*)d_in[0];
    const int*   w      = (const int*)d_in[1];
    const float* scales = (const float*)d_in[2];
    const float* bias   = (const float*)d_in[3];
    float*       out    = (float*)d_out;

    // attribute sets (idempotent; not allocations; graph-capture safe)
    cudaFuncSetAttribute(int4_linear_kernel,
                         cudaFuncAttributeMaxDynamicSharedMemorySize, SMEM_BYTES);
    cudaFuncSetAttribute(int4_linear_kernel,
                         cudaFuncAttributePreferredSharedMemoryCarveout, 100);

    convert_x_kernel<<<128, 256>>>(x);

    dim3 grid(N_DIM / BN);   // 448 CTAs; with 4 CTAs/SM all are co-resident
    int4_linear_kernel<<<grid, 128, SMEM_BYTES>>>(w, scales, bias, out);
}